// round 1
// baseline (speedup 1.0000x reference)
#include <cuda_runtime.h>
#include <math.h>
#include <stdint.h>

#define BB 1024
#define NN 512
#define EE 256
#define HH 128
#define AA 32

// ---------------- scratch (device globals; no allocation allowed) ----------
__device__ float g_xt[(size_t)BB * NN * HH];   // 256 MB: x_t [B,N,H]
__device__ float g_u [(size_t)BB * NN];        // u_t  [B,N]
__device__ float g_d2[(size_t)BB * HH];        // dec@W2 + b1 + b2
__device__ float g_ct[(size_t)BB * HH];        // c_t
__device__ float g_c2[(size_t)BB * HH];        // c_t@Wct + bct + bwt

// ---------------- kernel 1: d2 = dec@W2 + b1 + b2 ---------------------------
__global__ void k_d2(const float* __restrict__ dec, const float* __restrict__ W2,
                     const float* __restrict__ b1, const float* __restrict__ b2) {
    __shared__ float ds[HH];
    int b = blockIdx.x, h = threadIdx.x;
    ds[h] = dec[b * HH + h];
    __syncthreads();
    float acc = b1[h] + b2[h];
#pragma unroll 8
    for (int k = 0; k < HH; k++) acc = fmaf(ds[k], W2[k * HH + h], acc);
    g_d2[b * HH + h] = acc;
}

// ---------------- kernel 4: c2 = c_t@Wct + bct + bwt ------------------------
__global__ void k_c2(const float* __restrict__ Wct, const float* __restrict__ bct,
                     const float* __restrict__ bwt) {
    __shared__ float cs[HH];
    int b = blockIdx.x, h = threadIdx.x;
    cs[h] = g_ct[b * HH + h];
    __syncthreads();
    float acc = bct[h] + bwt[h];
#pragma unroll 8
    for (int k = 0; k < HH; k++) acc = fmaf(cs[k], Wct[k * HH + h], acc);
    g_c2[b * HH + h] = acc;
}

// ---------------- kernel 2: x_t = enc^T@W1 + d2 ; u = tanh(x@Wa+ba)@Va ------
// grid (N/64, B), block 256. Tile: 64 n  x 128 h, K = E = 256, KT = 16.
__global__ void __launch_bounds__(256)
k_gemm1(const float* __restrict__ enc, const float* __restrict__ W1,
        const float* __restrict__ Wa, const float* __restrict__ ba,
        const float* __restrict__ Va, const float* __restrict__ bva) {
    extern __shared__ float smem[];
    float* AS  = smem;                 // 2 * 16*64  = 2048
    float* BS  = AS + 2 * 16 * 64;     // 2 * 16*128 = 4096
    float* WAS = BS + 2 * 16 * 128;    // 128*32     = 4096
    float* XS  = WAS + HH * AA;        // 64*132     = 8448 (padded rows)
    float* D2S = XS + 64 * 132;        // 128
    float* BAS = D2S + HH;             // 32
    float* VAS = BAS + AA;             // 32

    const int tid = threadIdx.x;
    const int b   = blockIdx.y;
    const int n0  = blockIdx.x * 64;
    const int tr  = tid >> 4;          // 0..15 -> n = tr*4+i
    const int tc  = tid & 15;          // 0..15 -> h = tc*4+j and 64+tc*4+j

    for (int i = tid; i < HH * AA; i += 256) WAS[i] = Wa[i];
    if (tid < AA) { BAS[tid] = ba[tid]; VAS[tid] = Va[tid]; }
    if (tid < HH) D2S[tid] = g_d2[b * HH + tid];

    const float* Ab = enc + (size_t)b * EE * NN;
    const int ar = tid >> 4, ac = (tid & 15) * 4;   // A loader: k row, n col
    const int br = tid >> 4, bc = (tid & 15) * 8;   // B loader: k row, h col

    { // prologue: tile 0
        float4 a0 = *(const float4*)(Ab + ar * NN + n0 + ac);
        float4 w0 = *(const float4*)(W1 + br * HH + bc);
        float4 w1 = *(const float4*)(W1 + br * HH + bc + 4);
        *(float4*)(AS + ar * 64 + ac)      = a0;
        *(float4*)(BS + br * 128 + bc)     = w0;
        *(float4*)(BS + br * 128 + bc + 4) = w1;
    }
    __syncthreads();

    float acc[4][8];
#pragma unroll
    for (int i = 0; i < 4; i++)
#pragma unroll
        for (int j = 0; j < 8; j++) acc[i][j] = 0.f;

    int cur = 0;
    const int NKT = EE / 16;   // 16
    for (int kt = 0; kt < NKT; kt++) {
        float4 na, nb0, nb1;
        if (kt + 1 < NKT) {
            int k0 = (kt + 1) * 16;
            na  = *(const float4*)(Ab + (size_t)(k0 + ar) * NN + n0 + ac);
            nb0 = *(const float4*)(W1 + (k0 + br) * HH + bc);
            nb1 = *(const float4*)(W1 + (k0 + br) * HH + bc + 4);
        }
        const float* Ac = AS + cur * 16 * 64;
        const float* Bc = BS + cur * 16 * 128;
#pragma unroll
        for (int k = 0; k < 16; k++) {
            float4 av = *(const float4*)(Ac + k * 64 + tr * 4);
            float4 b0 = *(const float4*)(Bc + k * 128 + tc * 4);
            float4 b1v = *(const float4*)(Bc + k * 128 + 64 + tc * 4);
            float a_[4] = {av.x, av.y, av.z, av.w};
            float w_[8] = {b0.x, b0.y, b0.z, b0.w, b1v.x, b1v.y, b1v.z, b1v.w};
#pragma unroll
            for (int i = 0; i < 4; i++)
#pragma unroll
                for (int j = 0; j < 8; j++)
                    acc[i][j] = fmaf(a_[i], w_[j], acc[i][j]);
        }
        if (kt + 1 < NKT) {
            int nb = cur ^ 1;
            *(float4*)(AS + nb * 16 * 64 + ar * 64 + ac)       = na;
            *(float4*)(BS + nb * 16 * 128 + br * 128 + bc)     = nb0;
            *(float4*)(BS + nb * 16 * 128 + br * 128 + bc + 4) = nb1;
            __syncthreads();
            cur = nb;
        }
    }

    // epilogue: add d2, store x_t (gmem + smem)
#pragma unroll
    for (int i = 0; i < 4; i++) {
        int n = tr * 4 + i;
#pragma unroll
        for (int j = 0; j < 4; j++) acc[i][j]     += D2S[tc * 4 + j];
#pragma unroll
        for (int j = 0; j < 4; j++) acc[i][4 + j] += D2S[64 + tc * 4 + j];
        float4 v0 = make_float4(acc[i][0], acc[i][1], acc[i][2], acc[i][3]);
        float4 v1 = make_float4(acc[i][4], acc[i][5], acc[i][6], acc[i][7]);
        size_t off = ((size_t)(b * NN + n0 + n)) * HH;
        *(float4*)(g_xt + off + tc * 4)      = v0;
        *(float4*)(g_xt + off + 64 + tc * 4) = v1;
        *(float4*)(XS + n * 132 + tc * 4)      = v0;
        *(float4*)(XS + n * 132 + 64 + tc * 4) = v1;
    }
    __syncthreads();

    // u epilogue: u[n] = sum_a tanh(sum_h x[n,h]*Wa[h,a] + ba[a]) * Va[a] + bva
    {
        const int nl = tid >> 2;        // 0..63
        const int q  = tid & 3;         // a-quarter
        float s[8];
#pragma unroll
        for (int j = 0; j < 8; j++) s[j] = BAS[q * 8 + j];
        const float* xrow = XS + nl * 132;
#pragma unroll 4
        for (int h = 0; h < HH; h++) {
            float xv = xrow[h];
            float4 w0 = *(const float4*)(WAS + h * 32 + q * 8);
            float4 w1 = *(const float4*)(WAS + h * 32 + q * 8 + 4);
            s[0] = fmaf(xv, w0.x, s[0]); s[1] = fmaf(xv, w0.y, s[1]);
            s[2] = fmaf(xv, w0.z, s[2]); s[3] = fmaf(xv, w0.w, s[3]);
            s[4] = fmaf(xv, w1.x, s[4]); s[5] = fmaf(xv, w1.y, s[5]);
            s[6] = fmaf(xv, w1.z, s[6]); s[7] = fmaf(xv, w1.w, s[7]);
        }
        float u = 0.f;
#pragma unroll
        for (int j = 0; j < 8; j++) u = fmaf(tanhf(s[j]), VAS[q * 8 + j], u);
        u += __shfl_xor_sync(0xffffffffu, u, 1);
        u += __shfl_xor_sync(0xffffffffu, u, 2);
        if (q == 0) g_u[(size_t)b * NN + n0 + nl] = u + bva[0];
    }
}

// ---------------- kernel 3: softmax(u) and c_t = a^T x ----------------------
__global__ void k_softctx() {
    __shared__ float us[NN];
    __shared__ float red[256];
    __shared__ float cred[256];
    int b = blockIdx.x, tid = threadIdx.x;
    us[tid]       = g_u[(size_t)b * NN + tid];
    us[tid + 256] = g_u[(size_t)b * NN + tid + 256];
    __syncthreads();
    red[tid] = fmaxf(us[tid], us[tid + 256]);
    __syncthreads();
    for (int s = 128; s > 0; s >>= 1) {
        if (tid < s) red[tid] = fmaxf(red[tid], red[tid + s]);
        __syncthreads();
    }
    float mx = red[0];
    __syncthreads();
    float p0 = expf(us[tid] - mx), p1 = expf(us[tid + 256] - mx);
    us[tid] = p0; us[tid + 256] = p1;
    red[tid] = p0 + p1;
    __syncthreads();
    for (int s = 128; s > 0; s >>= 1) {
        if (tid < s) red[tid] += red[tid + s];
        __syncthreads();
    }
    float Z = red[0];
    int h = tid & 127, half = tid >> 7;
    const float* xb = g_xt + (size_t)b * NN * HH;
    float acc = 0.f;
    int nbeg = half * 256;
#pragma unroll 4
    for (int n = nbeg; n < nbeg + 256; n++)
        acc = fmaf(us[n], xb[(size_t)n * HH + h], acc);
    cred[tid] = acc;
    __syncthreads();
    if (tid < HH) g_ct[b * HH + tid] = (cred[tid] + cred[tid + 128]) / Z;
}

// ---------------- kernel 5: logits = tanh(x@Wwt + c2)@Vc + bvc --------------
// grid (N/64, B), block 256. Tile 64 n x 128 k_out, K = H = 128, KT = 32.
__global__ void __launch_bounds__(256)
k_gemm2(const float* __restrict__ Wwt, const float* __restrict__ Vc,
        const float* __restrict__ bvc, float* __restrict__ out) {
    extern __shared__ float smem[];
    float* AS  = smem;             // 2 * 32*68 = 4352 (k-major, padded)
    float* BS  = AS + 4352;        // 2 * 32*128 = 8192
    float* C2S = BS + 8192;        // 128
    float* VCS = C2S + HH;         // 128

    const int tid = threadIdx.x;
    const int b   = blockIdx.y;
    const int n0  = blockIdx.x * 64;
    const int tr  = tid >> 4, tc = tid & 15;

    if (tid < HH) { C2S[tid] = g_c2[b * HH + tid]; VCS[tid] = Vc[tid]; }

    const float* Ab = g_xt + ((size_t)(b * NN + n0)) * HH;
    const int anl = tid >> 2;            // n 0..63
    const int akq = (tid & 3) * 8;       // k group (8 floats)
    const int bwr = tid >> 3;            // 0..31
    const int bwc = (tid & 7) * 16;      // h col group (16 floats)

    { // prologue tile 0 (transpose A into k-major smem)
        float4 x0 = *(const float4*)(Ab + anl * HH + akq);
        float4 x1 = *(const float4*)(Ab + anl * HH + akq + 4);
        AS[(akq + 0) * 68 + anl] = x0.x; AS[(akq + 1) * 68 + anl] = x0.y;
        AS[(akq + 2) * 68 + anl] = x0.z; AS[(akq + 3) * 68 + anl] = x0.w;
        AS[(akq + 4) * 68 + anl] = x1.x; AS[(akq + 5) * 68 + anl] = x1.y;
        AS[(akq + 6) * 68 + anl] = x1.z; AS[(akq + 7) * 68 + anl] = x1.w;
#pragma unroll
        for (int v = 0; v < 4; v++)
            *(float4*)(BS + bwr * 128 + bwc + v * 4) =
                *(const float4*)(Wwt + bwr * HH + bwc + v * 4);
    }
    __syncthreads();

    float acc[4][8];
#pragma unroll
    for (int i = 0; i < 4; i++)
#pragma unroll
        for (int j = 0; j < 8; j++) acc[i][j] = 0.f;

    int cur = 0;
    const int NKT = HH / 32;   // 4
    for (int kt = 0; kt < NKT; kt++) {
        float4 px0, px1, pw[4];
        if (kt + 1 < NKT) {
            int k0 = (kt + 1) * 32;
            px0 = *(const float4*)(Ab + anl * HH + k0 + akq);
            px1 = *(const float4*)(Ab + anl * HH + k0 + akq + 4);
#pragma unroll
            for (int v = 0; v < 4; v++)
                pw[v] = *(const float4*)(Wwt + (k0 + bwr) * HH + bwc + v * 4);
        }
        const float* Ac = AS + cur * 32 * 68;
        const float* Bc = BS + cur * 32 * 128;
#pragma unroll
        for (int k = 0; k < 32; k++) {
            float4 av = *(const float4*)(Ac + k * 68 + tr * 4);
            float4 b0 = *(const float4*)(Bc + k * 128 + tc * 4);
            float4 b1v = *(const float4*)(Bc + k * 128 + 64 + tc * 4);
            float a_[4] = {av.x, av.y, av.z, av.w};
            float w_[8] = {b0.x, b0.y, b0.z, b0.w, b1v.x, b1v.y, b1v.z, b1v.w};
#pragma unroll
            for (int i = 0; i < 4; i++)
#pragma unroll
                for (int j = 0; j < 8; j++)
                    acc[i][j] = fmaf(a_[i], w_[j], acc[i][j]);
        }
        if (kt + 1 < NKT) {
            int nb = cur ^ 1;
            float* An = AS + nb * 32 * 68;
            float* Bn = BS + nb * 32 * 128;
            An[(akq + 0) * 68 + anl] = px0.x; An[(akq + 1) * 68 + anl] = px0.y;
            An[(akq + 2) * 68 + anl] = px0.z; An[(akq + 3) * 68 + anl] = px0.w;
            An[(akq + 4) * 68 + anl] = px1.x; An[(akq + 5) * 68 + anl] = px1.y;
            An[(akq + 6) * 68 + anl] = px1.z; An[(akq + 7) * 68 + anl] = px1.w;
#pragma unroll
            for (int v = 0; v < 4; v++)
                *(float4*)(Bn + bwr * 128 + bwc + v * 4) = pw[v];
            __syncthreads();
            cur = nb;
        }
    }

    // epilogue: tanh + dot with Vc, reduce over the 16 lanes sharing a row
    float bvcv = bvc[0];
#pragma unroll
    for (int i = 0; i < 4; i++) {
        float s = 0.f;
#pragma unroll
        for (int j = 0; j < 4; j++) {
            int h = tc * 4 + j;
            s = fmaf(tanhf(acc[i][j] + C2S[h]), VCS[h], s);
        }
#pragma unroll
        for (int j = 0; j < 4; j++) {
            int h = 64 + tc * 4 + j;
            s = fmaf(tanhf(acc[i][4 + j] + C2S[h]), VCS[h], s);
        }
        s += __shfl_xor_sync(0xffffffffu, s, 1);
        s += __shfl_xor_sync(0xffffffffu, s, 2);
        s += __shfl_xor_sync(0xffffffffu, s, 4);
        s += __shfl_xor_sync(0xffffffffu, s, 8);
        if (tc == 0)
            out[(size_t)b * NN + n0 + tr * 4 + i] = s + bvcv;
    }
}

// ---------------- kernel 6: log_softmax, mask, argmax, outputs --------------
__global__ void k_final(const float* __restrict__ demand, const float* __restrict__ load,
                        const void* __restrict__ veh_cap_raw, float* __restrict__ out) {
    __shared__ float sred[NN];
    __shared__ float sval[NN];
    __shared__ int   sidx[NN];
    __shared__ float s_ndsel;
    __shared__ int   s_ptr;
    int b = blockIdx.x, n = threadIdx.x;

    float logit = out[(size_t)b * NN + n];
    sred[n] = logit;
    __syncthreads();
    for (int s = 256; s > 0; s >>= 1) {
        if (n < s) sred[n] = fmaxf(sred[n], sred[n + s]);
        __syncthreads();
    }
    float mx = sred[0];
    __syncthreads();
    sred[n] = expf(logit - mx);
    __syncthreads();
    for (int s = 256; s > 0; s >>= 1) {
        if (n < s) sred[n] += sred[n + s];
        __syncthreads();
    }
    float lse = mx + logf(sred[0]);

    float dm = demand[(size_t)b * NN + n];
    float ld = load[b];
    float lp = logit - lse;
    if (n > 0 && (dm == 0.f || ld == 0.f)) lp = __int_as_float(0xff800000); // -inf
    out[(size_t)b * NN + n] = lp;

    sval[n] = lp; sidx[n] = n;
    __syncthreads();
    for (int s = 256; s > 0; s >>= 1) {
        if (n < s) {
            float v2 = sval[n + s]; int i2 = sidx[n + s];
            if (v2 > sval[n] || (v2 == sval[n] && i2 < sidx[n])) { sval[n] = v2; sidx[n] = i2; }
        }
        __syncthreads();
    }
    if (n == 0) {
        int ptr = sidx[0];
        float dsel = demand[(size_t)b * NN + ptr];
        // vehicle_capacity: accept int32 or float32 encoding
        float capf = *(const float*)veh_cap_raw;
        int   capi = *(const int*)veh_cap_raw;
        float cap = (capf > 0.5f && capf < 1.0e6f) ? capf : (float)capi;
        bool depot = (ptr == 0);
        float nload = depot ? cap : (ld - dsel);
        float ndsel = depot ? dsel : (dsel - nload);
        out[(size_t)BB * NN + b]      = (float)ptr;
        out[(size_t)BB * NN + BB + b] = nload;
        s_ptr = ptr; s_ndsel = ndsel;
    }
    __syncthreads();
    float ndv = (n == s_ptr) ? s_ndsel : dm;
    out[(size_t)BB * NN + 2 * (size_t)BB + (size_t)b * NN + n] = ndv;
}

// ---------------- launch ----------------------------------------------------
extern "C" void kernel_launch(void* const* d_in, const int* in_sizes, int n_in,
                              void* d_out, int out_size) {
    const float* dec  = (const float*)d_in[0];   // [B,1,H]
    const float* enc  = (const float*)d_in[1];   // [B,E,N]
    const float* load = (const float*)d_in[2];   // [B]
    const float* dem  = (const float*)d_in[3];   // [B,N]
    const float* W1   = (const float*)d_in[4];
    const float* b1   = (const float*)d_in[5];
    const float* W2   = (const float*)d_in[6];
    const float* b2   = (const float*)d_in[7];
    const float* Wwt  = (const float*)d_in[8];
    const float* bwt  = (const float*)d_in[9];
    const float* Wct  = (const float*)d_in[10];
    const float* bct  = (const float*)d_in[11];
    const float* Wa   = (const float*)d_in[12];
    const float* ba   = (const float*)d_in[13];
    const float* Va   = (const float*)d_in[14];
    const float* bva  = (const float*)d_in[15];
    const float* Vc   = (const float*)d_in[16];
    const float* bvc  = (const float*)d_in[17];
    const void*  vcap = (const void*)d_in[18];
    float* out = (float*)d_out;

    static int attr_done = 0;
    const int SMEM1 = (2*16*64 + 2*16*128 + HH*AA + 64*132 + HH + AA + AA) * 4;
    const int SMEM2 = (4352 + 8192 + HH + HH) * 4;
    if (!attr_done) {
        cudaFuncSetAttribute(k_gemm1, cudaFuncAttributeMaxDynamicSharedMemorySize, SMEM1);
        cudaFuncSetAttribute(k_gemm2, cudaFuncAttributeMaxDynamicSharedMemorySize, SMEM2);
        attr_done = 1;
    }

    k_d2<<<BB, HH>>>(dec, W2, b1, b2);
    k_gemm1<<<dim3(NN / 64, BB), 256, SMEM1>>>(enc, W1, Wa, ba, Va, bva);
    k_softctx<<<BB, 256>>>();
    k_c2<<<BB, HH>>>(Wct, bct, bwt);
    k_gemm2<<<dim3(NN / 64, BB), 256, SMEM2>>>(Wwt, Vc, bvc, out);
    k_final<<<BB, NN>>>(dem, load, vcap, out);
}

// round 2
// speedup vs baseline: 1.0779x; 1.0779x over previous
#include <cuda_runtime.h>
#include <math.h>
#include <stdint.h>

#define BB 1024
#define NN 512
#define EE 256
#define HH 128
#define AA 32

// ---------------- scratch (device globals) ----------------------------------
__device__ float g_u     [(size_t)BB * NN];   // u_t  [B,N]
__device__ float g_d2    [(size_t)BB * HH];   // dec@W2 + b1 + b2
__device__ float g_d2wa  [(size_t)BB * AA];   // d2@Wa + ba
__device__ float g_c2base[(size_t)BB * HH];   // d2@Wwt + bwt
__device__ float g_c2    [(size_t)BB * HH];   // c2base + c_t@Wct + bct
__device__ float g_w1wa  [(size_t)EE * AA];   // W1@Wa
__device__ float g_w1wwt [(size_t)EE * HH];   // W1@Wwt

// ---------------- k_prew: W1Wa = W1@Wa, W1Wwt = W1@Wwt ----------------------
__global__ void k_prew(const float* __restrict__ W1, const float* __restrict__ Wa,
                       const float* __restrict__ Wwt) {
    __shared__ float row[HH];
    int e = blockIdx.x, h = threadIdx.x;
    row[h] = W1[e * HH + h];
    __syncthreads();
    float acc = 0.f;
#pragma unroll 8
    for (int k = 0; k < HH; k++) acc = fmaf(row[k], Wwt[k * HH + h], acc);
    g_w1wwt[e * HH + h] = acc;
    if (h < AA) {
        float a2 = 0.f;
#pragma unroll 8
        for (int k = 0; k < HH; k++) a2 = fmaf(row[k], Wa[k * AA + h], a2);
        g_w1wa[e * AA + h] = a2;
    }
}

// ---------------- k_d2v: d2, d2@Wa+ba, d2@Wwt+bwt ---------------------------
__global__ void k_d2v(const float* __restrict__ dec, const float* __restrict__ W2,
                      const float* __restrict__ b1, const float* __restrict__ b2,
                      const float* __restrict__ Wa, const float* __restrict__ ba,
                      const float* __restrict__ Wwt, const float* __restrict__ bwt) {
    __shared__ float ds[HH], d2s[HH];
    int b = blockIdx.x, h = threadIdx.x;
    ds[h] = dec[b * HH + h];
    __syncthreads();
    float acc = b1[h] + b2[h];
#pragma unroll 8
    for (int k = 0; k < HH; k++) acc = fmaf(ds[k], W2[k * HH + h], acc);
    d2s[h] = acc;
    g_d2[b * HH + h] = acc;
    __syncthreads();
    float c2 = bwt[h];
#pragma unroll 8
    for (int k = 0; k < HH; k++) c2 = fmaf(d2s[k], Wwt[k * HH + h], c2);
    g_c2base[b * HH + h] = c2;
    if (h < AA) {
        float aw = ba[h];
#pragma unroll 8
        for (int k = 0; k < HH; k++) aw = fmaf(d2s[k], Wa[k * AA + h], aw);
        g_d2wa[b * AA + h] = aw;
    }
}

// ---------------- k_u: u = tanh(enc^T@W1Wa + d2Wa)@Va + bva -----------------
// grid (N/64, B), block 256. Tile 64 n x 32 a, K = E = 256, KT = 16.
__global__ void __launch_bounds__(256)
k_u(const float* __restrict__ enc, const float* __restrict__ Va,
    const float* __restrict__ bva) {
    __shared__ float WAS[EE * AA];        // 32 KB: full W1Wa
    __shared__ float AS[2][16 * 64];      // 8 KB: enc tiles
    __shared__ float D2A[AA], VAs[AA];

    const int tid = threadIdx.x;
    const int b   = blockIdx.y;
    const int n0  = blockIdx.x * 64;

    for (int i = tid * 4; i < EE * AA; i += 1024)
        *(float4*)(WAS + i) = *(const float4*)(g_w1wa + i);
    if (tid < AA) { D2A[tid] = g_d2wa[b * AA + tid]; VAs[tid] = Va[tid]; }

    const float* Ab = enc + (size_t)b * EE * NN + n0;
    const int ar = tid >> 4, ac = (tid & 15) * 4;
    *(float4*)(AS[0] + ar * 64 + ac) = *(const float4*)(Ab + (size_t)ar * NN + ac);
    __syncthreads();

    const int tn = tid >> 2;          // 0..63
    const int aq = (tid & 3) * 8;     // a group
    float acc[8];
#pragma unroll
    for (int j = 0; j < 8; j++) acc[j] = 0.f;

    int cur = 0;
    for (int kt = 0; kt < 16; kt++) {
        float4 na;
        if (kt < 15)
            na = *(const float4*)(Ab + (size_t)((kt + 1) * 16 + ar) * NN + ac);
        const float* Ac = AS[cur];
        const float* Wk = WAS + kt * 16 * AA;
#pragma unroll
        for (int k = 0; k < 16; k++) {
            float av  = Ac[k * 64 + tn];
            float4 w0 = *(const float4*)(Wk + k * AA + aq);
            float4 w1 = *(const float4*)(Wk + k * AA + aq + 4);
            acc[0] = fmaf(av, w0.x, acc[0]); acc[1] = fmaf(av, w0.y, acc[1]);
            acc[2] = fmaf(av, w0.z, acc[2]); acc[3] = fmaf(av, w0.w, acc[3]);
            acc[4] = fmaf(av, w1.x, acc[4]); acc[5] = fmaf(av, w1.y, acc[5]);
            acc[6] = fmaf(av, w1.z, acc[6]); acc[7] = fmaf(av, w1.w, acc[7]);
        }
        if (kt < 15) {
            *(float4*)(AS[cur ^ 1] + ar * 64 + ac) = na;
            __syncthreads();
            cur ^= 1;
        }
    }

    float u = 0.f;
#pragma unroll
    for (int j = 0; j < 8; j++)
        u = fmaf(tanhf(acc[j] + D2A[aq + j]), VAs[aq + j], u);
    u += __shfl_xor_sync(0xffffffffu, u, 1);
    u += __shfl_xor_sync(0xffffffffu, u, 2);
    if ((tid & 3) == 0) g_u[(size_t)b * NN + n0 + tn] = u + bva[0];
}

// ---------------- k_soft: softmax(u); e_c = a^T enc; c_t; c2 ----------------
__global__ void __launch_bounds__(256)
k_soft(const float* __restrict__ enc, const float* __restrict__ W1,
       const float* __restrict__ Wct, const float* __restrict__ bct) {
    __shared__ float us[NN];
    __shared__ float red[256];
    __shared__ float ec[EE];
    __shared__ float cts[HH];
    int b = blockIdx.x, tid = threadIdx.x;

    float u0 = g_u[(size_t)b * NN + tid];
    float u1 = g_u[(size_t)b * NN + 256 + tid];
    red[tid] = fmaxf(u0, u1);
    __syncthreads();
    for (int s = 128; s > 0; s >>= 1) {
        if (tid < s) red[tid] = fmaxf(red[tid], red[tid + s]);
        __syncthreads();
    }
    float mx = red[0];
    __syncthreads();
    float p0 = expf(u0 - mx), p1 = expf(u1 - mx);
    red[tid] = p0 + p1;
    __syncthreads();
    for (int s = 128; s > 0; s >>= 1) {
        if (tid < s) red[tid] += red[tid + s];
        __syncthreads();
    }
    float invZ = 1.f / red[0];
    us[tid] = p0 * invZ;
    us[tid + 256] = p1 * invZ;
    __syncthreads();

    // e_c[e] = sum_n a[n] * enc[b,e,n]; one warp per e row
    int w = tid >> 5, lane = tid & 31;
    const float* eb = enc + (size_t)b * EE * NN;
    for (int e = w; e < EE; e += 8) {
        const float* er = eb + (size_t)e * NN;
        float s = 0.f;
#pragma unroll 4
        for (int n = lane; n < NN; n += 32) s = fmaf(us[n], er[n], s);
        s += __shfl_xor_sync(0xffffffffu, s, 16);
        s += __shfl_xor_sync(0xffffffffu, s, 8);
        s += __shfl_xor_sync(0xffffffffu, s, 4);
        s += __shfl_xor_sync(0xffffffffu, s, 2);
        s += __shfl_xor_sync(0xffffffffu, s, 1);
        if (lane == 0) ec[e] = s;
    }
    __syncthreads();

    if (tid < HH) {
        float acc = g_d2[b * HH + tid];
#pragma unroll 8
        for (int k = 0; k < EE; k++) acc = fmaf(ec[k], W1[k * HH + tid], acc);
        cts[tid] = acc;
    }
    __syncthreads();
    if (tid < HH) {
        float c2 = g_c2base[b * HH + tid] + bct[tid];
#pragma unroll 8
        for (int k = 0; k < HH; k++) c2 = fmaf(cts[k], Wct[k * HH + tid], c2);
        g_c2[b * HH + tid] = c2;
    }
}

// ---------------- k_logits: logits = tanh(enc^T@W1Wwt + c2)@Vc + bvc --------
// grid (N/64, B), block 256. Tile 64 n x 128 h, K = E = 256, KT = 16.
__global__ void __launch_bounds__(256)
k_logits(const float* __restrict__ enc, const float* __restrict__ Vc,
         const float* __restrict__ bvc, float* __restrict__ out) {
    __shared__ float AS[2][16 * 64];     // enc tiles
    __shared__ float BS[2][16 * 128];    // W1Wwt tiles
    __shared__ float C2S[HH], VCS[HH];

    const int tid = threadIdx.x;
    const int b   = blockIdx.y;
    const int n0  = blockIdx.x * 64;
    const int tr  = tid >> 4;          // n = tr*4+i
    const int tc  = tid & 15;          // h = tc*4+j, 64+tc*4+j

    if (tid < HH) { C2S[tid] = g_c2[b * HH + tid]; VCS[tid] = Vc[tid]; }

    const float* Ab = enc + (size_t)b * EE * NN + n0;
    const int ar = tid >> 4, ac = (tid & 15) * 4;
    const int br = tid >> 4, bc = (tid & 15) * 8;

    {
        *(float4*)(AS[0] + ar * 64 + ac)       = *(const float4*)(Ab + (size_t)ar * NN + ac);
        *(float4*)(BS[0] + br * 128 + bc)      = *(const float4*)(g_w1wwt + br * HH + bc);
        *(float4*)(BS[0] + br * 128 + bc + 4)  = *(const float4*)(g_w1wwt + br * HH + bc + 4);
    }
    __syncthreads();

    float acc[4][8];
#pragma unroll
    for (int i = 0; i < 4; i++)
#pragma unroll
        for (int j = 0; j < 8; j++) acc[i][j] = 0.f;

    int cur = 0;
    for (int kt = 0; kt < 16; kt++) {
        float4 na, nb0, nb1;
        if (kt < 15) {
            int k0 = (kt + 1) * 16;
            na  = *(const float4*)(Ab + (size_t)(k0 + ar) * NN + ac);
            nb0 = *(const float4*)(g_w1wwt + (k0 + br) * HH + bc);
            nb1 = *(const float4*)(g_w1wwt + (k0 + br) * HH + bc + 4);
        }
        const float* Ac = AS[cur];
        const float* Bc = BS[cur];
#pragma unroll
        for (int k = 0; k < 16; k++) {
            float4 av  = *(const float4*)(Ac + k * 64 + tr * 4);
            float4 b0  = *(const float4*)(Bc + k * 128 + tc * 4);
            float4 b1v = *(const float4*)(Bc + k * 128 + 64 + tc * 4);
            float a_[4] = {av.x, av.y, av.z, av.w};
            float w_[8] = {b0.x, b0.y, b0.z, b0.w, b1v.x, b1v.y, b1v.z, b1v.w};
#pragma unroll
            for (int i = 0; i < 4; i++)
#pragma unroll
                for (int j = 0; j < 8; j++)
                    acc[i][j] = fmaf(a_[i], w_[j], acc[i][j]);
        }
        if (kt < 15) {
            int nb = cur ^ 1;
            *(float4*)(AS[nb] + ar * 64 + ac)      = na;
            *(float4*)(BS[nb] + br * 128 + bc)     = nb0;
            *(float4*)(BS[nb] + br * 128 + bc + 4) = nb1;
            __syncthreads();
            cur = nb;
        }
    }

    // epilogue: tanh + dot with Vc, reduce over 16 lanes sharing a row
    float bvcv = bvc[0];
#pragma unroll
    for (int i = 0; i < 4; i++) {
        float s = 0.f;
#pragma unroll
        for (int j = 0; j < 4; j++) {
            int h = tc * 4 + j;
            s = fmaf(tanhf(acc[i][j] + C2S[h]), VCS[h], s);
        }
#pragma unroll
        for (int j = 0; j < 4; j++) {
            int h = 64 + tc * 4 + j;
            s = fmaf(tanhf(acc[i][4 + j] + C2S[h]), VCS[h], s);
        }
        s += __shfl_xor_sync(0xffffffffu, s, 1);
        s += __shfl_xor_sync(0xffffffffu, s, 2);
        s += __shfl_xor_sync(0xffffffffu, s, 4);
        s += __shfl_xor_sync(0xffffffffu, s, 8);
        if (tc == 0)
            out[(size_t)b * NN + n0 + tr * 4 + i] = s + bvcv;
    }
}

// ---------------- k_final: log_softmax, mask, argmax, outputs ---------------
__global__ void k_final(const float* __restrict__ demand, const float* __restrict__ load,
                        const void* __restrict__ veh_cap_raw, float* __restrict__ out) {
    __shared__ float sred[NN];
    __shared__ float sval[NN];
    __shared__ int   sidx[NN];
    __shared__ float s_ndsel;
    __shared__ int   s_ptr;
    int b = blockIdx.x, n = threadIdx.x;

    float logit = out[(size_t)b * NN + n];
    sred[n] = logit;
    __syncthreads();
    for (int s = 256; s > 0; s >>= 1) {
        if (n < s) sred[n] = fmaxf(sred[n], sred[n + s]);
        __syncthreads();
    }
    float mx = sred[0];
    __syncthreads();
    sred[n] = expf(logit - mx);
    __syncthreads();
    for (int s = 256; s > 0; s >>= 1) {
        if (n < s) sred[n] += sred[n + s];
        __syncthreads();
    }
    float lse = mx + logf(sred[0]);

    float dm = demand[(size_t)b * NN + n];
    float ld = load[b];
    float lp = logit - lse;
    if (n > 0 && (dm == 0.f || ld == 0.f)) lp = __int_as_float(0xff800000); // -inf
    out[(size_t)b * NN + n] = lp;

    sval[n] = lp; sidx[n] = n;
    __syncthreads();
    for (int s = 256; s > 0; s >>= 1) {
        if (n < s) {
            float v2 = sval[n + s]; int i2 = sidx[n + s];
            if (v2 > sval[n] || (v2 == sval[n] && i2 < sidx[n])) { sval[n] = v2; sidx[n] = i2; }
        }
        __syncthreads();
    }
    if (n == 0) {
        int ptr = sidx[0];
        float dsel = demand[(size_t)b * NN + ptr];
        float capf = *(const float*)veh_cap_raw;
        int   capi = *(const int*)veh_cap_raw;
        float cap = (capf > 0.5f && capf < 1.0e6f) ? capf : (float)capi;
        bool depot = (ptr == 0);
        float nload = depot ? cap : (ld - dsel);
        float ndsel = depot ? dsel : (dsel - nload);
        out[(size_t)BB * NN + b]      = (float)ptr;
        out[(size_t)BB * NN + BB + b] = nload;
        s_ptr = ptr; s_ndsel = ndsel;
    }
    __syncthreads();
    float ndv = (n == s_ptr) ? s_ndsel : dm;
    out[(size_t)BB * NN + 2 * (size_t)BB + (size_t)b * NN + n] = ndv;
}

// ---------------- launch ----------------------------------------------------
extern "C" void kernel_launch(void* const* d_in, const int* in_sizes, int n_in,
                              void* d_out, int out_size) {
    const float* dec  = (const float*)d_in[0];   // [B,1,H]
    const float* enc  = (const float*)d_in[1];   // [B,E,N]
    const float* load = (const float*)d_in[2];   // [B]
    const float* dem  = (const float*)d_in[3];   // [B,N]
    const float* W1   = (const float*)d_in[4];
    const float* b1   = (const float*)d_in[5];
    const float* W2   = (const float*)d_in[6];
    const float* b2   = (const float*)d_in[7];
    const float* Wwt  = (const float*)d_in[8];
    const float* bwt  = (const float*)d_in[9];
    const float* Wct  = (const float*)d_in[10];
    const float* bct  = (const float*)d_in[11];
    const float* Wa   = (const float*)d_in[12];
    const float* ba   = (const float*)d_in[13];
    const float* Va   = (const float*)d_in[14];
    const float* bva  = (const float*)d_in[15];
    const float* Vc   = (const float*)d_in[16];
    const float* bvc  = (const float*)d_in[17];
    const void*  vcap = (const void*)d_in[18];
    float* out = (float*)d_out;

    k_prew<<<EE, HH>>>(W1, Wa, Wwt);
    k_d2v<<<BB, HH>>>(dec, W2, b1, b2, Wa, ba, Wwt, bwt);
    k_u<<<dim3(NN / 64, BB), 256>>>(enc, Va, bva);
    k_soft<<<BB, 256>>>(enc, W1, Wct, bct);
    k_logits<<<dim3(NN / 64, BB), 256>>>(enc, Vc, bvc, out);
    k_final<<<BB, NN>>>(dem, load, vcap, out);
}

// round 3
// speedup vs baseline: 1.7939x; 1.6643x over previous
#include <cuda_runtime.h>
#include <math.h>
#include <stdint.h>

#define BB 1024
#define NN 512
#define EE 256
#define HH 128
#define AA 32
#define KC 32
#define APAD 136
#define BPAD 136
#define WPAD 40

// ---------------- scratch (device globals) ----------------------------------
__device__ float g_u     [(size_t)BB * NN];   // u_t  [B,N]
__device__ float g_d2    [(size_t)BB * HH];   // dec@W2 + b1 + b2
__device__ float g_d2wa  [(size_t)BB * AA];   // d2@Wa + ba
__device__ float g_c2base[(size_t)BB * HH];   // d2@Wwt + bwt
__device__ float g_c2    [(size_t)BB * HH];   // c2base + c_t@Wct + bct
__device__ float g_wwt_hi[(size_t)EE * HH];   // tf32-hi of W1@Wwt  [e][h]
__device__ float g_wwt_lo[(size_t)EE * HH];   // tf32-lo
__device__ float g_wa_hi [(size_t)EE * AA];   // tf32-hi of W1@Wa   [e][a]
__device__ float g_wa_lo [(size_t)EE * AA];   // tf32-lo

__device__ __forceinline__ uint32_t f2tf32(float x) {
    uint32_t r;
    asm("cvt.rna.tf32.f32 %0, %1;" : "=r"(r) : "f"(x));
    return r;
}

#define MMA_TF32(C, A, B0, B1)                                                  \
    asm volatile(                                                               \
        "mma.sync.aligned.m16n8k8.row.col.f32.tf32.tf32.f32 "                   \
        "{%0,%1,%2,%3}, {%4,%5,%6,%7}, {%8,%9}, {%0,%1,%2,%3};"                 \
        : "+f"((C)[0]), "+f"((C)[1]), "+f"((C)[2]), "+f"((C)[3])                \
        : "r"((A)[0]), "r"((A)[1]), "r"((A)[2]), "r"((A)[3]),                   \
          "r"(B0), "r"(B1))

// ---------------- k_prew: W1@Wwt and W1@Wa, tf32 hi/lo split ----------------
__global__ void k_prew(const float* __restrict__ W1, const float* __restrict__ Wa,
                       const float* __restrict__ Wwt) {
    __shared__ float row[HH];
    int e = blockIdx.x, h = threadIdx.x;
    row[h] = W1[e * HH + h];
    __syncthreads();
    float acc = 0.f;
#pragma unroll 8
    for (int k = 0; k < HH; k++) acc = fmaf(row[k], Wwt[k * HH + h], acc);
    uint32_t hi = f2tf32(acc);
    float hif = __uint_as_float(hi);
    g_wwt_hi[e * HH + h] = hif;
    g_wwt_lo[e * HH + h] = __uint_as_float(f2tf32(acc - hif));
    if (h < AA) {
        float a2 = 0.f;
#pragma unroll 8
        for (int k = 0; k < HH; k++) a2 = fmaf(row[k], Wa[k * AA + h], a2);
        uint32_t ahi = f2tf32(a2);
        float ahif = __uint_as_float(ahi);
        g_wa_hi[e * AA + h] = ahif;
        g_wa_lo[e * AA + h] = __uint_as_float(f2tf32(a2 - ahif));
    }
}

// ---------------- k_d2v: d2, d2@Wa+ba, d2@Wwt+bwt ---------------------------
__global__ void k_d2v(const float* __restrict__ dec, const float* __restrict__ W2,
                      const float* __restrict__ b1, const float* __restrict__ b2,
                      const float* __restrict__ Wa, const float* __restrict__ ba,
                      const float* __restrict__ Wwt, const float* __restrict__ bwt) {
    __shared__ float ds[HH], d2s[HH];
    int b = blockIdx.x, h = threadIdx.x;
    ds[h] = dec[b * HH + h];
    __syncthreads();
    float acc = b1[h] + b2[h];
#pragma unroll 8
    for (int k = 0; k < HH; k++) acc = fmaf(ds[k], W2[k * HH + h], acc);
    d2s[h] = acc;
    g_d2[b * HH + h] = acc;
    __syncthreads();
    float c2 = bwt[h];
#pragma unroll 8
    for (int k = 0; k < HH; k++) c2 = fmaf(d2s[k], Wwt[k * HH + h], c2);
    g_c2base[b * HH + h] = c2;
    if (h < AA) {
        float aw = ba[h];
#pragma unroll 8
        for (int k = 0; k < HH; k++) aw = fmaf(d2s[k], Wa[k * AA + h], aw);
        g_d2wa[b * AA + h] = aw;
    }
}

// ---------------- k_u_mma: u = tanh(enc^T@W1Wa + d2Wa)@Va + bva -------------
// grid (N/128, B), block 256. Tile 128 n x 32 a; warp tile 16n x 32a.
__global__ void __launch_bounds__(256)
k_u_mma(const float* __restrict__ enc, const float* __restrict__ Va,
        const float* __restrict__ bva) {
    __shared__ float AS[KC * APAD];
    __shared__ float BAH[KC * WPAD];
    __shared__ float BAL[KC * WPAD];
    __shared__ float D2A[AA], VAs[AA];

    const int tid  = threadIdx.x;
    const int lane = tid & 31, w = tid >> 5;
    const int gid  = lane >> 2, tig = lane & 3;
    const int b    = blockIdx.y;
    const int n0   = blockIdx.x * 128;
    const int m0   = w * 16;

    if (tid < AA) { D2A[tid] = g_d2wa[b * AA + tid]; VAs[tid] = Va[tid]; }
    const float bva0 = bva[0];

    float c[4][4];
#pragma unroll
    for (int nt = 0; nt < 4; nt++)
#pragma unroll
        for (int q = 0; q < 4; q++) c[nt][q] = 0.f;

    const float* Ab = enc + (size_t)b * EE * NN + n0;
    const int lk = tid >> 3, ln = (tid & 7) * 4;

    for (int kt = 0; kt < EE / KC; kt++) {
        __syncthreads();
        const float* arow = Ab + (size_t)(kt * KC + lk) * NN;
#pragma unroll
        for (int j = 0; j < 4; j++)
            *(float4*)(AS + lk * APAD + ln + 32 * j) = *(const float4*)(arow + ln + 32 * j);
        *(float4*)(BAH + lk * WPAD + ln) = *(const float4*)(g_wa_hi + (size_t)(kt * KC + lk) * AA + ln);
        *(float4*)(BAL + lk * WPAD + ln) = *(const float4*)(g_wa_lo + (size_t)(kt * KC + lk) * AA + ln);
        __syncthreads();

#pragma unroll
        for (int k8 = 0; k8 < 4; k8++) {
            const int kk = k8 * 8 + tig;
            const int m  = m0 + gid;
            float x0 = AS[kk * APAD + m];
            float x1 = AS[kk * APAD + m + 8];
            float x2 = AS[(kk + 4) * APAD + m];
            float x3 = AS[(kk + 4) * APAD + m + 8];
            uint32_t ah[4], al[4];
            ah[0] = f2tf32(x0); al[0] = f2tf32(x0 - __uint_as_float(ah[0]));
            ah[1] = f2tf32(x1); al[1] = f2tf32(x1 - __uint_as_float(ah[1]));
            ah[2] = f2tf32(x2); al[2] = f2tf32(x2 - __uint_as_float(ah[2]));
            ah[3] = f2tf32(x3); al[3] = f2tf32(x3 - __uint_as_float(ah[3]));
#pragma unroll
            for (int nt = 0; nt < 4; nt++) {
                const int a = nt * 8 + gid;
                uint32_t bh0 = __float_as_uint(BAH[kk * WPAD + a]);
                uint32_t bh1 = __float_as_uint(BAH[(kk + 4) * WPAD + a]);
                uint32_t bl0 = __float_as_uint(BAL[kk * WPAD + a]);
                uint32_t bl1 = __float_as_uint(BAL[(kk + 4) * WPAD + a]);
                MMA_TF32(c[nt], ah, bh0, bh1);
                MMA_TF32(c[nt], al, bh0, bh1);
                MMA_TF32(c[nt], ah, bl0, bl1);
            }
        }
    }

    // epilogue: tanh + dot Va, reduce over the 4 lanes sharing a row
    float s0 = 0.f, s1 = 0.f;
#pragma unroll
    for (int nt = 0; nt < 4; nt++)
#pragma unroll
        for (int q = 0; q < 2; q++) {
            int a = nt * 8 + 2 * tig + q;
            s0 = fmaf(tanhf(c[nt][q]     + D2A[a]), VAs[a], s0);
            s1 = fmaf(tanhf(c[nt][2 + q] + D2A[a]), VAs[a], s1);
        }
    s0 += __shfl_xor_sync(0xffffffffu, s0, 1);
    s0 += __shfl_xor_sync(0xffffffffu, s0, 2);
    s1 += __shfl_xor_sync(0xffffffffu, s1, 1);
    s1 += __shfl_xor_sync(0xffffffffu, s1, 2);
    if (tig == 0) {
        g_u[(size_t)b * NN + n0 + m0 + gid]     = s0 + bva0;
        g_u[(size_t)b * NN + n0 + m0 + gid + 8] = s1 + bva0;
    }
}

// ---------------- k_soft: softmax(u); e_c = a^T enc; c_t; c2 ----------------
__global__ void __launch_bounds__(256)
k_soft(const float* __restrict__ enc, const float* __restrict__ W1,
       const float* __restrict__ Wct, const float* __restrict__ bct) {
    __shared__ float us[NN];
    __shared__ float red[256];
    __shared__ float ec[EE];
    __shared__ float cts[HH];
    int b = blockIdx.x, tid = threadIdx.x;

    float u0 = g_u[(size_t)b * NN + tid];
    float u1 = g_u[(size_t)b * NN + 256 + tid];
    red[tid] = fmaxf(u0, u1);
    __syncthreads();
    for (int s = 128; s > 0; s >>= 1) {
        if (tid < s) red[tid] = fmaxf(red[tid], red[tid + s]);
        __syncthreads();
    }
    float mx = red[0];
    __syncthreads();
    float p0 = expf(u0 - mx), p1 = expf(u1 - mx);
    red[tid] = p0 + p1;
    __syncthreads();
    for (int s = 128; s > 0; s >>= 1) {
        if (tid < s) red[tid] += red[tid + s];
        __syncthreads();
    }
    float invZ = 1.f / red[0];
    us[tid] = p0 * invZ;
    us[tid + 256] = p1 * invZ;
    __syncthreads();

    int w = tid >> 5, lane = tid & 31;
    const float* eb = enc + (size_t)b * EE * NN;
    for (int e = w; e < EE; e += 8) {
        const float* er = eb + (size_t)e * NN;
        float s = 0.f;
#pragma unroll 4
        for (int n = lane; n < NN; n += 32) s = fmaf(us[n], er[n], s);
        s += __shfl_xor_sync(0xffffffffu, s, 16);
        s += __shfl_xor_sync(0xffffffffu, s, 8);
        s += __shfl_xor_sync(0xffffffffu, s, 4);
        s += __shfl_xor_sync(0xffffffffu, s, 2);
        s += __shfl_xor_sync(0xffffffffu, s, 1);
        if (lane == 0) ec[e] = s;
    }
    __syncthreads();

    if (tid < HH) {
        float acc = g_d2[b * HH + tid];
#pragma unroll 8
        for (int k = 0; k < EE; k++) acc = fmaf(ec[k], W1[k * HH + tid], acc);
        cts[tid] = acc;
    }
    __syncthreads();
    if (tid < HH) {
        float c2 = g_c2base[b * HH + tid] + bct[tid];
#pragma unroll 8
        for (int k = 0; k < HH; k++) c2 = fmaf(cts[k], Wct[k * HH + tid], c2);
        g_c2[b * HH + tid] = c2;
    }
}

// ---------------- k_logits_mma: logits = tanh(enc^T@W1Wwt + c2)@Vc + bvc ----
// grid (N/128, B), block 256. Tile 128 n x 128 h; warp tile 32n x 64h.
__global__ void __launch_bounds__(256)
k_logits_mma(const float* __restrict__ enc, const float* __restrict__ Vc,
             const float* __restrict__ bvc, float* __restrict__ out) {
    extern __shared__ float sm[];
    float* AS  = sm;                    // KC * APAD
    float* BH  = AS + KC * APAD;        // KC * BPAD
    float* BL  = BH + KC * BPAD;        // KC * BPAD
    float* C2S = BL + KC * BPAD;        // 128
    float* VCS = C2S + HH;              // 128
    float* EP  = VCS + HH;              // 128 * 2

    const int tid  = threadIdx.x;
    const int lane = tid & 31, w = tid >> 5;
    const int gid  = lane >> 2, tig = lane & 3;
    const int b    = blockIdx.y;
    const int n0   = blockIdx.x * 128;
    const int m0   = (w >> 1) * 32;
    const int h0   = (w & 1) * 64;

    if (tid < HH) { C2S[tid] = g_c2[b * HH + tid]; VCS[tid] = Vc[tid]; }

    float c[2][8][4];
#pragma unroll
    for (int mt = 0; mt < 2; mt++)
#pragma unroll
        for (int nt = 0; nt < 8; nt++)
#pragma unroll
            for (int q = 0; q < 4; q++) c[mt][nt][q] = 0.f;

    const float* Ab = enc + (size_t)b * EE * NN + n0;
    const int lk = tid >> 3, ln = (tid & 7) * 4;

    for (int kt = 0; kt < EE / KC; kt++) {
        __syncthreads();
        const float* arow = Ab + (size_t)(kt * KC + lk) * NN;
        const float* bhrow = g_wwt_hi + (size_t)(kt * KC + lk) * HH;
        const float* blrow = g_wwt_lo + (size_t)(kt * KC + lk) * HH;
#pragma unroll
        for (int j = 0; j < 4; j++) {
            *(float4*)(AS + lk * APAD + ln + 32 * j) = *(const float4*)(arow + ln + 32 * j);
            *(float4*)(BH + lk * BPAD + ln + 32 * j) = *(const float4*)(bhrow + ln + 32 * j);
            *(float4*)(BL + lk * BPAD + ln + 32 * j) = *(const float4*)(blrow + ln + 32 * j);
        }
        __syncthreads();

#pragma unroll
        for (int k8 = 0; k8 < 4; k8++) {
            const int kk = k8 * 8 + tig;
            uint32_t ah[2][4], al[2][4];
#pragma unroll
            for (int mt = 0; mt < 2; mt++) {
                const int m = m0 + mt * 16 + gid;
                float x0 = AS[kk * APAD + m];
                float x1 = AS[kk * APAD + m + 8];
                float x2 = AS[(kk + 4) * APAD + m];
                float x3 = AS[(kk + 4) * APAD + m + 8];
                ah[mt][0] = f2tf32(x0); al[mt][0] = f2tf32(x0 - __uint_as_float(ah[mt][0]));
                ah[mt][1] = f2tf32(x1); al[mt][1] = f2tf32(x1 - __uint_as_float(ah[mt][1]));
                ah[mt][2] = f2tf32(x2); al[mt][2] = f2tf32(x2 - __uint_as_float(ah[mt][2]));
                ah[mt][3] = f2tf32(x3); al[mt][3] = f2tf32(x3 - __uint_as_float(ah[mt][3]));
            }
#pragma unroll
            for (int nt = 0; nt < 8; nt++) {
                const int h = h0 + nt * 8 + gid;
                uint32_t bh0 = __float_as_uint(BH[kk * BPAD + h]);
                uint32_t bh1 = __float_as_uint(BH[(kk + 4) * BPAD + h]);
                uint32_t bl0 = __float_as_uint(BL[kk * BPAD + h]);
                uint32_t bl1 = __float_as_uint(BL[(kk + 4) * BPAD + h]);
#pragma unroll
                for (int mt = 0; mt < 2; mt++) {
                    MMA_TF32(c[mt][nt], ah[mt], bh0, bh1);
                    MMA_TF32(c[mt][nt], al[mt], bh0, bh1);
                    MMA_TF32(c[mt][nt], ah[mt], bl0, bl1);
                }
            }
        }
    }

    // epilogue: tanh + dot Vc; reduce 4 lanes per row, then 2 warp-cols via smem
#pragma unroll
    for (int mt = 0; mt < 2; mt++) {
        float s0 = 0.f, s1 = 0.f;
#pragma unroll
        for (int nt = 0; nt < 8; nt++)
#pragma unroll
            for (int q = 0; q < 2; q++) {
                int h = h0 + nt * 8 + 2 * tig + q;
                s0 = fmaf(tanhf(c[mt][nt][q]     + C2S[h]), VCS[h], s0);
                s1 = fmaf(tanhf(c[mt][nt][2 + q] + C2S[h]), VCS[h], s1);
            }
        s0 += __shfl_xor_sync(0xffffffffu, s0, 1);
        s0 += __shfl_xor_sync(0xffffffffu, s0, 2);
        s1 += __shfl_xor_sync(0xffffffffu, s1, 1);
        s1 += __shfl_xor_sync(0xffffffffu, s1, 2);
        if (tig == 0) {
            int r = m0 + mt * 16 + gid;
            EP[r * 2 + (w & 1)]       = s0;
            EP[(r + 8) * 2 + (w & 1)] = s1;
        }
    }
    __syncthreads();
    if (tid < 128)
        out[(size_t)b * NN + n0 + tid] = EP[tid * 2] + EP[tid * 2 + 1] + bvc[0];
}

// ---------------- k_final: log_softmax, mask, argmax, outputs ---------------
__global__ void k_final(const float* __restrict__ demand, const float* __restrict__ load,
                        const void* __restrict__ veh_cap_raw, float* __restrict__ out) {
    __shared__ float sred[NN];
    __shared__ float sval[NN];
    __shared__ int   sidx[NN];
    __shared__ float s_ndsel;
    __shared__ int   s_ptr;
    int b = blockIdx.x, n = threadIdx.x;

    float logit = out[(size_t)b * NN + n];
    sred[n] = logit;
    __syncthreads();
    for (int s = 256; s > 0; s >>= 1) {
        if (n < s) sred[n] = fmaxf(sred[n], sred[n + s]);
        __syncthreads();
    }
    float mx = sred[0];
    __syncthreads();
    sred[n] = expf(logit - mx);
    __syncthreads();
    for (int s = 256; s > 0; s >>= 1) {
        if (n < s) sred[n] += sred[n + s];
        __syncthreads();
    }
    float lse = mx + logf(sred[0]);

    float dm = demand[(size_t)b * NN + n];
    float ld = load[b];
    float lp = logit - lse;
    if (n > 0 && (dm == 0.f || ld == 0.f)) lp = __int_as_float(0xff800000); // -inf
    out[(size_t)b * NN + n] = lp;

    sval[n] = lp; sidx[n] = n;
    __syncthreads();
    for (int s = 256; s > 0; s >>= 1) {
        if (n < s) {
            float v2 = sval[n + s]; int i2 = sidx[n + s];
            if (v2 > sval[n] || (v2 == sval[n] && i2 < sidx[n])) { sval[n] = v2; sidx[n] = i2; }
        }
        __syncthreads();
    }
    if (n == 0) {
        int ptr = sidx[0];
        float dsel = demand[(size_t)b * NN + ptr];
        float capf = *(const float*)veh_cap_raw;
        int   capi = *(const int*)veh_cap_raw;
        float cap = (capf > 0.5f && capf < 1.0e6f) ? capf : (float)capi;
        bool depot = (ptr == 0);
        float nload = depot ? cap : (ld - dsel);
        float ndsel = depot ? dsel : (dsel - nload);
        out[(size_t)BB * NN + b]      = (float)ptr;
        out[(size_t)BB * NN + BB + b] = nload;
        s_ptr = ptr; s_ndsel = ndsel;
    }
    __syncthreads();
    float ndv = (n == s_ptr) ? s_ndsel : dm;
    out[(size_t)BB * NN + 2 * (size_t)BB + (size_t)b * NN + n] = ndv;
}

// ---------------- launch ----------------------------------------------------
extern "C" void kernel_launch(void* const* d_in, const int* in_sizes, int n_in,
                              void* d_out, int out_size) {
    const float* dec  = (const float*)d_in[0];
    const float* enc  = (const float*)d_in[1];
    const float* load = (const float*)d_in[2];
    const float* dem  = (const float*)d_in[3];
    const float* W1   = (const float*)d_in[4];
    const float* b1   = (const float*)d_in[5];
    const float* W2   = (const float*)d_in[6];
    const float* b2   = (const float*)d_in[7];
    const float* Wwt  = (const float*)d_in[8];
    const float* bwt  = (const float*)d_in[9];
    const float* Wct  = (const float*)d_in[10];
    const float* bct  = (const float*)d_in[11];
    const float* Wa   = (const float*)d_in[12];
    const float* ba   = (const float*)d_in[13];
    const float* Va   = (const float*)d_in[14];
    const float* bva  = (const float*)d_in[15];
    const float* Vc   = (const float*)d_in[16];
    const float* bvc  = (const float*)d_in[17];
    const void*  vcap = (const void*)d_in[18];
    float* out = (float*)d_out;

    const int SMEM_L = (KC * APAD + 2 * KC * BPAD + HH + HH + 2 * 128) * 4;
    static int attr_done = 0;
    if (!attr_done) {
        cudaFuncSetAttribute(k_logits_mma, cudaFuncAttributeMaxDynamicSharedMemorySize, SMEM_L);
        attr_done = 1;
    }

    k_prew<<<EE, HH>>>(W1, Wa, Wwt);
    k_d2v<<<BB, HH>>>(dec, W2, b1, b2, Wa, ba, Wwt, bwt);
    k_u_mma<<<dim3(NN / 128, BB), 256>>>(enc, Va, bva);
    k_soft<<<BB, 256>>>(enc, W1, Wct, bct);
    k_logits_mma<<<dim3(NN / 128, BB), 256, SMEM_L>>>(enc, Vc, bvc, out);
    k_final<<<BB, NN>>>(dem, load, vcap, out);
}